// round 16
// baseline (speedup 1.0000x reference)
#include <cuda_runtime.h>
#include <cuda_fp16.h>

#define NN 100000
#define EE 1600000
#define DD 64
#define HH 64
#define GG 64
#define CC 2

// ---- scratch (device globals; referenced ONLY inside device code) ----
__device__ __align__(16) float  d_hbuf[NN * HH];  // layer activations (fp32)
__device__ __align__(16) __half d_gh[NN * HH];    // g = (h@W)*dinv  (fp16)
__device__ int   d_cnt[NN];
__device__ int   d_rowstart[NN + 1];
__device__ int   d_cursor[NN];
__device__ int   d_csrsrc[EE];
__device__ float d_sums[GG * HH];
__device__ float d_cnts[GG];

// ---------------------------------------------------------------------------
__global__ void k_zero_cnt() {
    int i = blockIdx.x * blockDim.x + threadIdx.x;
    if (i < NN) d_cnt[i] = 0;
}

__global__ void k_count(const int* __restrict__ edge_index) {
    int t = blockIdx.x * blockDim.x + threadIdx.x;
    if (t >= EE / 4) return;
    int4 d4 = reinterpret_cast<const int4*>(edge_index + EE)[t];
    if ((unsigned)d4.x < NN) atomicAdd(&d_cnt[d4.x], 1);
    if ((unsigned)d4.y < NN) atomicAdd(&d_cnt[d4.y], 1);
    if ((unsigned)d4.z < NN) atomicAdd(&d_cnt[d4.z], 1);
    if ((unsigned)d4.w < NN) atomicAdd(&d_cnt[d4.w], 1);
}

#define SCAN_T 1024
__global__ void k_scan() {
    __shared__ int ssum[SCAN_T];
    int t = threadIdx.x;
    const int per = (NN + SCAN_T - 1) / SCAN_T;
    int lo = t * per;
    int hi = lo + per < NN ? lo + per : NN;

    int s = 0;
    for (int i = lo; i < hi; i++) s += d_cnt[i];
    ssum[t] = s;
    __syncthreads();

    for (int off = 1; off < SCAN_T; off <<= 1) {
        int v = 0;
        if (t >= off) v = ssum[t - off];
        __syncthreads();
        if (t >= off) ssum[t] += v;
        __syncthreads();
    }

    int run = ssum[t] - s;
    for (int i = lo; i < hi; i++) {
        d_rowstart[i] = run;
        d_cursor[i] = run;
        run += d_cnt[i];
    }
    if (t == SCAN_T - 1) d_rowstart[NN] = run;
}

__global__ void k_fill(const int* __restrict__ edge_index) {
    int t = blockIdx.x * blockDim.x + threadIdx.x;
    if (t >= EE / 4) return;
    int4 s4 = reinterpret_cast<const int4*>(edge_index)[t];
    int4 d4 = reinterpret_cast<const int4*>(edge_index + EE)[t];
    int p0 = -1, p1 = -1, p2 = -1, p3 = -1;
    if ((unsigned)d4.x < NN) p0 = atomicAdd(&d_cursor[d4.x], 1);
    if ((unsigned)d4.y < NN) p1 = atomicAdd(&d_cursor[d4.y], 1);
    if ((unsigned)d4.z < NN) p2 = atomicAdd(&d_cursor[d4.z], 1);
    if ((unsigned)d4.w < NN) p3 = atomicAdd(&d_cursor[d4.w], 1);
    if (p0 >= 0) d_csrsrc[p0] = s4.x;
    if (p1 >= 0) d_csrsrc[p1] = s4.y;
    if (p2 >= 0) d_csrsrc[p2] = s4.z;
    if (p3 >= 0) d_csrsrc[p3] = s4.w;
}

// ---------------------------------------------------------------------------
// GEMM (fp32 compute): g[row] = (X[row] @ W) * rsqrt(deg+1), stored as fp16.
// FIRST: X = external x; else X = d_hbuf (device-side reference only).
template <bool FIRST>
__global__ void k_gemm(const float* __restrict__ Xext,
                       const float* __restrict__ W) {
    __shared__ float Xs[64][65];
    __shared__ __align__(16) float Ws[64 * 64];

    int tid = threadIdx.x;
    int row0 = blockIdx.x * 64;
    const float* X = FIRST ? Xext : (const float*)d_hbuf;

    #pragma unroll
    for (int i = 0; i < 16; i++)
        Ws[tid + i * 256] = W[tid + i * 256];

    #pragma unroll
    for (int i = 0; i < 16; i++) {
        int idx = tid + i * 256;
        int r = idx >> 6, c = idx & 63;
        int grow = row0 + r;
        Xs[r][c] = (grow < NN) ? X[grow * 64 + c] : 0.0f;
    }
    __syncthreads();

    int txg = tid & 15;
    int ty  = tid >> 4;

    float a0x = 0, a0y = 0, a0z = 0, a0w = 0;
    float a1x = 0, a1y = 0, a1z = 0, a1w = 0;
    float a2x = 0, a2y = 0, a2z = 0, a2w = 0;
    float a3x = 0, a3y = 0, a3z = 0, a3w = 0;

    #pragma unroll
    for (int k = 0; k < 64; k++) {
        float4 w = reinterpret_cast<const float4*>(Ws)[k * 16 + txg];
        float x0 = Xs[ty * 4 + 0][k];
        float x1 = Xs[ty * 4 + 1][k];
        float x2 = Xs[ty * 4 + 2][k];
        float x3 = Xs[ty * 4 + 3][k];
        a0x = fmaf(x0, w.x, a0x); a0y = fmaf(x0, w.y, a0y);
        a0z = fmaf(x0, w.z, a0z); a0w = fmaf(x0, w.w, a0w);
        a1x = fmaf(x1, w.x, a1x); a1y = fmaf(x1, w.y, a1y);
        a1z = fmaf(x1, w.z, a1z); a1w = fmaf(x1, w.w, a1w);
        a2x = fmaf(x2, w.x, a2x); a2y = fmaf(x2, w.y, a2y);
        a2z = fmaf(x2, w.z, a2z); a2w = fmaf(x2, w.w, a2w);
        a3x = fmaf(x3, w.x, a3x); a3y = fmaf(x3, w.y, a3y);
        a3z = fmaf(x3, w.z, a3z); a3w = fmaf(x3, w.w, a3w);
    }

    #pragma unroll
    for (int r = 0; r < 4; r++) {
        int grow = row0 + ty * 4 + r;
        if (grow >= NN) continue;
        float dinv = rsqrtf((float)d_cnt[grow] + 1.0f);
        float4 v;
        if (r == 0) v = make_float4(a0x, a0y, a0z, a0w);
        else if (r == 1) v = make_float4(a1x, a1y, a1z, a1w);
        else if (r == 2) v = make_float4(a2x, a2y, a2z, a2w);
        else v = make_float4(a3x, a3y, a3z, a3w);
        __half2 p0 = __floats2half2_rn(v.x * dinv, v.y * dinv);
        __half2 p1 = __floats2half2_rn(v.z * dinv, v.w * dinv);
        uint2 u;
        u.x = *reinterpret_cast<unsigned*>(&p0);
        u.y = *reinterpret_cast<unsigned*>(&p1);
        reinterpret_cast<uint2*>(d_gh)[grow * 16 + txg] = u;  // 8B store
    }
}

// ---------------------------------------------------------------------------
__device__ __forceinline__ void acc_add8(float* a, uint4 u) {
    float2 f0 = __half22float2(*reinterpret_cast<__half2*>(&u.x));
    float2 f1 = __half22float2(*reinterpret_cast<__half2*>(&u.y));
    float2 f2 = __half22float2(*reinterpret_cast<__half2*>(&u.z));
    float2 f3 = __half22float2(*reinterpret_cast<__half2*>(&u.w));
    a[0] += f0.x; a[1] += f0.y; a[2] += f1.x; a[3] += f1.y;
    a[4] += f2.x; a[5] += f2.y; a[6] += f3.x; a[7] += f3.y;
}

// CSR gather aggregation, WARP PER NODE:
//   32 lanes = 4 edge-groups x 8 channel-lanes. Each group strides the edge
//   list by 4 (unrolled x2) -> 8+ independent gathers in flight per warp.
//   fp32 register accumulators; shfl_xor(8,16) folds groups; group 0 adds
//   the self-loop term, applies dinv/bias/relu and stores h.
__global__ void k_aggr(const float* __restrict__ b) {
    int gt = blockIdx.x * blockDim.x + threadIdx.x;
    int n = gt >> 5;
    if (n >= NN) return;
    int lane = threadIdx.x & 31;
    int q = lane & 7;        // channel chunk (8 halves)
    int grp = lane >> 3;     // edge group 0..3

    const uint4* g4 = reinterpret_cast<const uint4*>(d_gh);
    float acc[8] = {0, 0, 0, 0, 0, 0, 0, 0};

    int s = d_rowstart[n];
    int e = d_rowstart[n + 1];

    int i = s + grp;
    for (; i + 4 < e; i += 8) {              // two group-strided edges per iter
        int s0 = d_csrsrc[i];
        int s1 = d_csrsrc[i + 4];
        uint4 v0 = g4[s0 * 8 + q];
        uint4 v1 = g4[s1 * 8 + q];
        acc_add8(acc, v0);
        acc_add8(acc, v1);
    }
    if (i < e) acc_add8(acc, g4[d_csrsrc[i] * 8 + q]);

    // fold the 4 edge-groups (lanes differing in bits 3..4)
    #pragma unroll
    for (int k = 0; k < 8; k++) {
        acc[k] += __shfl_xor_sync(0xffffffff, acc[k], 8);
        acc[k] += __shfl_xor_sync(0xffffffff, acc[k], 16);
    }

    if (grp == 0) {
        acc_add8(acc, g4[n * 8 + q]);        // self-loop term
        float dinv = rsqrtf((float)(e - s) + 1.0f);
        const float4 bb0 = reinterpret_cast<const float4*>(b)[q * 2 + 0];
        const float4 bb1 = reinterpret_cast<const float4*>(b)[q * 2 + 1];
        float4 o0, o1;
        o0.x = fmaxf(fmaf(acc[0], dinv, bb0.x), 0.0f);
        o0.y = fmaxf(fmaf(acc[1], dinv, bb0.y), 0.0f);
        o0.z = fmaxf(fmaf(acc[2], dinv, bb0.z), 0.0f);
        o0.w = fmaxf(fmaf(acc[3], dinv, bb0.w), 0.0f);
        o1.x = fmaxf(fmaf(acc[4], dinv, bb1.x), 0.0f);
        o1.y = fmaxf(fmaf(acc[5], dinv, bb1.y), 0.0f);
        o1.z = fmaxf(fmaf(acc[6], dinv, bb1.z), 0.0f);
        o1.w = fmaxf(fmaf(acc[7], dinv, bb1.w), 0.0f);
        reinterpret_cast<float4*>(d_hbuf)[n * 16 + q * 2 + 0] = o0;
        reinterpret_cast<float4*>(d_hbuf)[n * 16 + q * 2 + 1] = o1;
    }
}

// ---------------------------------------------------------------------------
__global__ void k_zero_pool() {
    int i = blockIdx.x * blockDim.x + threadIdx.x;
    if (i < GG * HH) d_sums[i] = 0.0f;
    if (i < GG) d_cnts[i] = 0.0f;
}

#define POOL_NPT 16
__global__ void k_pool(const int* __restrict__ batch) {
    int t = blockIdx.x * blockDim.x + threadIdx.x;
    int c = t & 63;
    int nb = t >> 6;
    int n0 = nb * POOL_NPT;
    if (n0 >= NN) return;

    int cur = -1;
    float s = 0.0f;
    float cnt = 0.0f;
    #pragma unroll
    for (int i = 0; i < POOL_NPT; i++) {
        int n = n0 + i;
        if (n >= NN) break;
        int g = batch[n];
        if (g != cur) {
            if (cur >= 0 && (unsigned)cur < GG) {
                atomicAdd(&d_sums[cur * 64 + c], s);
                if (c == 0) atomicAdd(&d_cnts[cur], cnt);
            }
            cur = g; s = 0.0f; cnt = 0.0f;
        }
        s += d_hbuf[n * 64 + c];
        cnt += 1.0f;
    }
    if (cur >= 0 && (unsigned)cur < GG) {
        atomicAdd(&d_sums[cur * 64 + c], s);
        if (c == 0) atomicAdd(&d_cnts[cur], cnt);
    }
}

__global__ void k_final(const float* __restrict__ Wlin,
                        const float* __restrict__ blin,
                        float* __restrict__ out) {
    int t = threadIdx.x;
    if (t < GG * CC) {
        int g = t / CC, c = t % CC;
        float inv = 1.0f / fmaxf(d_cnts[g], 1.0f);
        float acc = blin[c];
        #pragma unroll
        for (int h = 0; h < HH; h++)
            acc = fmaf(d_sums[g * 64 + h] * inv, Wlin[h * CC + c], acc);
        out[g * CC + c] = acc;
    }
}

// ---------------------------------------------------------------------------
extern "C" void kernel_launch(void* const* d_in, const int* in_sizes, int n_in,
                              void* d_out, int out_size) {
    const float* x    = (const float*)d_in[0];
    const int*   ei   = (const int*)  d_in[1];
    const int*   batch= (const int*)  d_in[2];
    const float* W0   = (const float*)d_in[3];
    const float* b0   = (const float*)d_in[4];
    const float* W1   = (const float*)d_in[5];
    const float* b1   = (const float*)d_in[6];
    const float* W2   = (const float*)d_in[7];
    const float* b2   = (const float*)d_in[8];
    const float* Wlin = (const float*)d_in[9];
    const float* blin = (const float*)d_in[10];
    float* out = (float*)d_out;

    const int gemmB = (NN + 63) / 64;
    const int nodeB = (NN + 255) / 256;
    const int e4B   = (EE / 4 + 255) / 256;
    const int aggrB = (int)(((long long)NN * 32 + 255) / 256);   // 12500
    const int poolB = (((NN + POOL_NPT - 1) / POOL_NPT) * 64 + 255) / 256;

    // ---- CSR build (amortized over 3 layers) ----
    k_zero_cnt<<<nodeB, 256>>>();
    k_count<<<e4B, 256>>>(ei);
    k_scan<<<1, SCAN_T>>>();
    k_fill<<<e4B, 256>>>(ei);

    // layer 0
    k_gemm<true><<<gemmB, 256>>>(x, W0);
    k_aggr<<<aggrB, 256>>>(b0);

    // layer 1
    k_gemm<false><<<gemmB, 256>>>(nullptr, W1);
    k_aggr<<<aggrB, 256>>>(b1);

    // layer 2
    k_gemm<false><<<gemmB, 256>>>(nullptr, W2);
    k_aggr<<<aggrB, 256>>>(b2);

    // pooling + head
    k_zero_pool<<<(GG * HH + 255) / 256, 256>>>();
    k_pool<<<poolB, 256>>>(batch);
    k_final<<<1, 128>>>(Wlin, blin, out);
}

// round 17
// speedup vs baseline: 1.6358x; 1.6358x over previous
#include <cuda_runtime.h>
#include <cuda_fp16.h>

#define NN 100000
#define EE 1600000
#define DD 64
#define HH 64
#define GG 64
#define CC 2

// ---- scratch (device globals; referenced ONLY inside device code) ----
__device__ __align__(16) __half d_gh[NN * HH];    // g = (h@W)*dinv   (fp16)
__device__ __align__(16) __half d_acch[NN * HH];  // accumulator      (fp16)
__device__ float d_deg[NN];
__device__ float d_sums[GG * HH];
__device__ float d_cnts[GG];

// ---------------------------------------------------------------------------
__global__ void k_zero_deg() {
    int i = blockIdx.x * blockDim.x + threadIdx.x;
    if (i < NN) d_deg[i] = 0.0f;
}

__global__ void k_deg(const int* __restrict__ edge_index) {
    int t = blockIdx.x * blockDim.x + threadIdx.x;
    if (t >= EE / 4) return;
    int4 d4 = reinterpret_cast<const int4*>(edge_index + EE)[t];
    if ((unsigned)d4.x < NN) atomicAdd(&d_deg[d4.x], 1.0f);
    if ((unsigned)d4.y < NN) atomicAdd(&d_deg[d4.y], 1.0f);
    if ((unsigned)d4.z < NN) atomicAdd(&d_deg[d4.z], 1.0f);
    if ((unsigned)d4.w < NN) atomicAdd(&d_deg[d4.w], 1.0f);
}

// ---------------------------------------------------------------------------
// GEMM (fp32 compute): g = (X @ W) * rsqrt(deg+1), stored fp16 to d_gh AND
// d_acch (self-loop seed). FIRST: X = external x. Otherwise X =
// relu(d_acch * dinv + bprev)  — previous layer's finalize fused into staging.
// All device-global buffers referenced inside device code only.
template <bool FIRST>
__global__ void k_gemm(const float* __restrict__ Xext,
                       const float* __restrict__ W,
                       const float* __restrict__ bprev) {
    __shared__ float Xs[64][65];
    __shared__ __align__(16) float Ws[64 * 64];

    int tid = threadIdx.x;
    int row0 = blockIdx.x * 64;

    #pragma unroll
    for (int i = 0; i < 16; i++)
        Ws[tid + i * 256] = W[tid + i * 256];

    if (FIRST) {
        #pragma unroll
        for (int i = 0; i < 16; i++) {
            int idx = tid + i * 256;
            int r = idx >> 6, c = idx & 63;
            int grow = row0 + r;
            Xs[r][c] = (grow < NN) ? Xext[grow * 64 + c] : 0.0f;
        }
    } else {
        // 64 rows x 32 half2 = 2048 items
        #pragma unroll
        for (int i = 0; i < 8; i++) {
            int idx = tid + i * 256;
            int r = idx >> 5, c2 = idx & 31;
            int grow = row0 + r;
            float vx = 0.0f, vy = 0.0f;
            if (grow < NN) {
                __half2 hv = reinterpret_cast<const __half2*>(d_acch)[grow * 32 + c2];
                float2 f = __half22float2(hv);
                float dinv = rsqrtf(d_deg[grow] + 1.0f);
                vx = fmaxf(fmaf(f.x, dinv, bprev[c2 * 2 + 0]), 0.0f);
                vy = fmaxf(fmaf(f.y, dinv, bprev[c2 * 2 + 1]), 0.0f);
            }
            Xs[r][c2 * 2 + 0] = vx;
            Xs[r][c2 * 2 + 1] = vy;
        }
    }
    __syncthreads();

    int txg = tid & 15;
    int ty  = tid >> 4;

    float a0x = 0, a0y = 0, a0z = 0, a0w = 0;
    float a1x = 0, a1y = 0, a1z = 0, a1w = 0;
    float a2x = 0, a2y = 0, a2z = 0, a2w = 0;
    float a3x = 0, a3y = 0, a3z = 0, a3w = 0;

    #pragma unroll
    for (int k = 0; k < 64; k++) {
        float4 w = reinterpret_cast<const float4*>(Ws)[k * 16 + txg];
        float x0 = Xs[ty * 4 + 0][k];
        float x1 = Xs[ty * 4 + 1][k];
        float x2 = Xs[ty * 4 + 2][k];
        float x3 = Xs[ty * 4 + 3][k];
        a0x = fmaf(x0, w.x, a0x); a0y = fmaf(x0, w.y, a0y);
        a0z = fmaf(x0, w.z, a0z); a0w = fmaf(x0, w.w, a0w);
        a1x = fmaf(x1, w.x, a1x); a1y = fmaf(x1, w.y, a1y);
        a1z = fmaf(x1, w.z, a1z); a1w = fmaf(x1, w.w, a1w);
        a2x = fmaf(x2, w.x, a2x); a2y = fmaf(x2, w.y, a2y);
        a2z = fmaf(x2, w.z, a2z); a2w = fmaf(x2, w.w, a2w);
        a3x = fmaf(x3, w.x, a3x); a3y = fmaf(x3, w.y, a3y);
        a3z = fmaf(x3, w.z, a3z); a3w = fmaf(x3, w.w, a3w);
    }

    #pragma unroll
    for (int r = 0; r < 4; r++) {
        int grow = row0 + ty * 4 + r;
        if (grow >= NN) continue;
        float dinv = rsqrtf(d_deg[grow] + 1.0f);
        float4 v;
        if (r == 0) v = make_float4(a0x, a0y, a0z, a0w);
        else if (r == 1) v = make_float4(a1x, a1y, a1z, a1w);
        else if (r == 2) v = make_float4(a2x, a2y, a2z, a2w);
        else v = make_float4(a3x, a3y, a3z, a3w);
        __half2 p0 = __floats2half2_rn(v.x * dinv, v.y * dinv);
        __half2 p1 = __floats2half2_rn(v.z * dinv, v.w * dinv);
        uint2 u;
        u.x = *reinterpret_cast<unsigned*>(&p0);
        u.y = *reinterpret_cast<unsigned*>(&p1);
        reinterpret_cast<uint2*>(d_gh)[grow * 16 + txg] = u;
        reinterpret_cast<uint2*>(d_acch)[grow * 16 + txg] = u;  // self-loop seed
    }
}

// ---------------------------------------------------------------------------
// Scatter: 8 threads per edge, each owns 8 halves (16B):
//   acc[dst] += g[src]  via red.global.add.noftz.v4.f16x2 (16B vector red).
__global__ void k_scat(const int* __restrict__ edge_index) {
    int t = blockIdx.x * blockDim.x + threadIdx.x;   // < EE*8 = 12.8M
    if (t >= EE * 8) return;
    int e = t >> 3;
    int q = t & 7;

    int src = edge_index[e];
    int dst = edge_index[EE + e];
    if ((unsigned)src >= NN || (unsigned)dst >= NN) return;

    uint4 v = reinterpret_cast<const uint4*>(d_gh)[src * 8 + q];
    __half* a = d_acch + dst * 64 + q * 8;
    asm volatile("red.global.add.noftz.v4.f16x2 [%0], {%1, %2, %3, %4};"
                 :: "l"(a), "r"(v.x), "r"(v.y), "r"(v.z), "r"(v.w)
                 : "memory");
}

// ---------------------------------------------------------------------------
__global__ void k_zero_pool() {
    int i = blockIdx.x * blockDim.x + threadIdx.x;
    if (i < GG * HH) d_sums[i] = 0.0f;
    if (i < GG) d_cnts[i] = 0.0f;
}

// Fused finalize(layer2) + mean-pool numerators. One column x 16 consecutive
// nodes per thread; run-accumulate per graph (batch sorted), 1 atomic/run.
#define POOL_NPT 16
__global__ void k_pool(const int* __restrict__ batch,
                       const float* __restrict__ b2) {
    int t = blockIdx.x * blockDim.x + threadIdx.x;
    int c = t & 63;
    int nb = t >> 6;
    int n0 = nb * POOL_NPT;
    if (n0 >= NN) return;

    int cur = -1;
    float s = 0.0f;
    float cnt = 0.0f;
    float bc = b2[c];
    #pragma unroll
    for (int i = 0; i < POOL_NPT; i++) {
        int n = n0 + i;
        if (n >= NN) break;
        int g = batch[n];
        if (g != cur) {
            if (cur >= 0 && (unsigned)cur < GG) {
                atomicAdd(&d_sums[cur * 64 + c], s);
                if (c == 0) atomicAdd(&d_cnts[cur], cnt);
            }
            cur = g; s = 0.0f; cnt = 0.0f;
        }
        float acc = __half2float(d_acch[n * 64 + c]);
        float dinv = rsqrtf(d_deg[n] + 1.0f);
        s += fmaxf(fmaf(acc, dinv, bc), 0.0f);
        cnt += 1.0f;
    }
    if (cur >= 0 && (unsigned)cur < GG) {
        atomicAdd(&d_sums[cur * 64 + c], s);
        if (c == 0) atomicAdd(&d_cnts[cur], cnt);
    }
}

__global__ void k_final(const float* __restrict__ Wlin,
                        const float* __restrict__ blin,
                        float* __restrict__ out) {
    int t = threadIdx.x;
    if (t < GG * CC) {
        int g = t / CC, c = t % CC;
        float inv = 1.0f / fmaxf(d_cnts[g], 1.0f);
        float acc = blin[c];
        #pragma unroll
        for (int h = 0; h < HH; h++)
            acc = fmaf(d_sums[g * 64 + h] * inv, Wlin[h * CC + c], acc);
        out[g * CC + c] = acc;
    }
}

// ---------------------------------------------------------------------------
extern "C" void kernel_launch(void* const* d_in, const int* in_sizes, int n_in,
                              void* d_out, int out_size) {
    const float* x    = (const float*)d_in[0];
    const int*   ei   = (const int*)  d_in[1];
    const int*   batch= (const int*)  d_in[2];
    const float* W0   = (const float*)d_in[3];
    const float* b0   = (const float*)d_in[4];
    const float* W1   = (const float*)d_in[5];
    const float* b1   = (const float*)d_in[6];
    const float* W2   = (const float*)d_in[7];
    const float* b2   = (const float*)d_in[8];
    const float* Wlin = (const float*)d_in[9];
    const float* blin = (const float*)d_in[10];
    float* out = (float*)d_out;

    const int gemmB = (NN + 63) / 64;
    const int nodeB = (NN + 255) / 256;
    const int e4B   = (EE / 4 + 255) / 256;
    const int scatB = (EE * 8 + 255) / 256;      // 50000
    const int poolB = (((NN + POOL_NPT - 1) / POOL_NPT) * 64 + 255) / 256;

    k_zero_deg<<<nodeB, 256>>>();
    k_deg<<<e4B, 256>>>(ei);

    // layer 0
    k_gemm<true><<<gemmB, 256>>>(x, W0, nullptr);
    k_scat<<<scatB, 256>>>(ei);

    // layer 1 (layer-0 finalize fused into staging)
    k_gemm<false><<<gemmB, 256>>>(nullptr, W1, b0);
    k_scat<<<scatB, 256>>>(ei);

    // layer 2
    k_gemm<false><<<gemmB, 256>>>(nullptr, W2, b1);
    k_scat<<<scatB, 256>>>(ei);

    // pooling (layer-2 finalize fused) + head
    k_zero_pool<<<(GG * HH + 255) / 256, 256>>>();
    k_pool<<<poolB, 256>>>(batch, b2);
    k_final<<<1, 128>>>(Wlin, blin, out);
}